// round 9
// baseline (speedup 1.0000x reference)
#include <cuda_runtime.h>
#include <math.h>

// SpectralAngleLoss R9: warp-per-row, warp-private smem histogram, ZERO atomics.
// Collisions resolved with match_any + ballot-elimination rounds (plain LDS/STS).
// Gather-form norms, fused last-CTA mean. B=8192 rows, N=256, 2000 bins.

#define N_PEAKS   256
#define NUM_BINS  2000
#define NB_PAD    2048
#define MAX_ROWS  8192
#define THREADS   128            // 4 warps = 4 rows per CTA
#define ROWS_PER_CTA 4

__device__ float        g_partials[MAX_ROWS];
__device__ unsigned int g_count = 0;

__device__ __forceinline__ int mz_bin(float mz) {
    int b = (int)(mz * 2000.0f);             // trunc toward zero == astype(int32)
    return min(max(b, 0), NUM_BINS - 1);
}

// Scatter one element per lane into warp-private histogram, NO atomics.
// match_any finds same-bin groups; ballot-elimination serializes group members
// (warp-uniform loop, trip count = max group size, expected ~2).
__device__ __forceinline__ void scatter_batch(float* __restrict__ h,
                                              int bin, float val, unsigned lane) {
    unsigned m = __match_any_sync(0xFFFFFFFFu, bin);
    bool done = false;
    while (true) {
        unsigned notdone = __ballot_sync(0xFFFFFFFFu, !done);
        if (!notdone) break;                 // warp-uniform exit
        int leader = __ffs(m & notdone) - 1; // first pending member of my group
        if (!done && (int)lane == leader) {
            h[bin] += val;                   // plain LDS+FADD+STS, race-free
            done = true;
        }
    }
}

__global__ __launch_bounds__(THREADS)
void sal_kernel(const float* __restrict__ pred_mz,
                const float* __restrict__ pred_int,
                const float* __restrict__ targ_mz,
                const float* __restrict__ targ_int,
                const float* __restrict__ targ_mask,
                float* __restrict__ out, int rows)
{
    __shared__ __align__(16) float hist[ROWS_PER_CTA][NB_PAD];   // 32 KB
    __shared__ float fred[THREADS];
    __shared__ int   is_last;

    const int tid  = threadIdx.x;
    const int w    = tid >> 5;
    const unsigned lane = tid & 31;
    const int row  = blockIdx.x * ROWS_PER_CTA + w;

    if (row < rows) {
        float* h = hist[w];

        // ---- zero warp-private histogram (16 STS.128/lane, exact)
        {
            float4 z = make_float4(0.f, 0.f, 0.f, 0.f);
            float4* h4 = (float4*)h;
            #pragma unroll
            for (int i = 0; i < NB_PAD / 4 / 32; i++)
                h4[lane + i * 32] = z;
        }

        // ---- coalesced float4 loads: 8 elements per lane
        float ip[8], itm[8];
        int   bp[8], bt[8];
        {
            const int base4 = row * (N_PEAKS / 4);
            const float4* pmz = (const float4*)pred_mz   + base4;
            const float4* pin = (const float4*)pred_int  + base4;
            const float4* tmz = (const float4*)targ_mz   + base4;
            const float4* tin = (const float4*)targ_int  + base4;
            const float4* tms = (const float4*)targ_mask + base4;
            #pragma unroll
            for (int g = 0; g < 2; g++) {
                int i4 = lane + 32 * g;
                float4 a = pmz[i4]; float4 b = pin[i4];
                float4 c = tmz[i4]; float4 d = tin[i4]; float4 e = tms[i4];
                bp[4*g+0]=mz_bin(a.x); bp[4*g+1]=mz_bin(a.y);
                bp[4*g+2]=mz_bin(a.z); bp[4*g+3]=mz_bin(a.w);
                ip[4*g+0]=b.x; ip[4*g+1]=b.y; ip[4*g+2]=b.z; ip[4*g+3]=b.w;
                bt[4*g+0]=mz_bin(c.x); bt[4*g+1]=mz_bin(c.y);
                bt[4*g+2]=mz_bin(c.z); bt[4*g+3]=mz_bin(c.w);
                itm[4*g+0]=d.x*e.x; itm[4*g+1]=d.y*e.y;
                itm[4*g+2]=d.z*e.z; itm[4*g+3]=d.w*e.w;
            }
        }
        __syncwarp();

        // ---- scatter TARGET (no atomics)
        #pragma unroll
        for (int k = 0; k < 8; k++) scatter_batch(h, bt[k], itm[k], lane);
        __syncwarp();

        // ---- gather dot & tn from T
        float dot = 0.f, tn = 0.f, pn = 0.f;
        #pragma unroll
        for (int k = 0; k < 8; k++) tn  = fmaf(itm[k], h[bt[k]], tn);
        #pragma unroll
        for (int k = 0; k < 8; k++) dot = fmaf(ip[k],  h[bp[k]], dot);
        __syncwarp();

        // ---- clean touched T bins, scatter PRED, gather pn
        #pragma unroll
        for (int k = 0; k < 8; k++) h[bt[k]] = 0.0f;
        __syncwarp();
        #pragma unroll
        for (int k = 0; k < 8; k++) scatter_batch(h, bp[k], ip[k], lane);
        __syncwarp();
        #pragma unroll
        for (int k = 0; k < 8; k++) pn = fmaf(ip[k], h[bp[k]], pn);

        // ---- warp reduce + angle
        #pragma unroll
        for (int o = 16; o > 0; o >>= 1) {
            dot += __shfl_xor_sync(0xFFFFFFFFu, dot, o);
            tn  += __shfl_xor_sync(0xFFFFFFFFu, tn,  o);
            pn  += __shfl_xor_sync(0xFFFFFFFFu, pn,  o);
        }
        if (lane == 0) {
            const float eps = 1e-8f;
            float c = dot / (fmaxf(sqrtf(pn), eps) * fmaxf(sqrtf(tn), eps));
            c = fminf(fmaxf(c, -1.0f), 1.0f);
            g_partials[row] = acosf(c);
        }
    }
    __syncthreads();

    // ---- fused final mean: last-arriving CTA reduces all partials
    if (tid == 0) {
        __threadfence();
        unsigned old = atomicAdd(&g_count, 1u);
        is_last = (old == gridDim.x - 1) ? 1 : 0;
    }
    __syncthreads();

    if (is_last) {
        const float4* gp4 = (const float4*)g_partials;
        float v = 0.f;
        #pragma unroll
        for (int i = 0; i < MAX_ROWS / 4 / THREADS; i++) {   // 16 iters
            float4 a4 = __ldcv(&gp4[tid + i * THREADS]);
            v += (a4.x + a4.y) + (a4.z + a4.w);
        }
        fred[tid] = v;
        __syncthreads();
        #pragma unroll
        for (int o = THREADS / 2; o > 0; o >>= 1) {
            if (tid < o) fred[tid] += fred[tid + o];
            __syncthreads();
        }
        if (tid == 0) {
            out[0] = fred[0] / ((float)rows * 3.14159265358979323846f);
            g_count = 0;                     // reset for next graph replay
        }
    }
}

extern "C" void kernel_launch(void* const* d_in, const int* in_sizes, int n_in,
                              void* d_out, int out_size)
{
    const float* pred_mz   = (const float*)d_in[0];
    const float* pred_int  = (const float*)d_in[1];
    const float* targ_mz   = (const float*)d_in[2];
    const float* targ_int  = (const float*)d_in[3];
    const float* targ_mask = (const float*)d_in[4];
    float* out = (float*)d_out;

    int rows = in_sizes[0] / N_PEAKS;
    if (rows > MAX_ROWS) rows = MAX_ROWS;
    int grid = (rows + ROWS_PER_CTA - 1) / ROWS_PER_CTA;

    sal_kernel<<<grid, THREADS>>>(pred_mz, pred_int, targ_mz, targ_int,
                                  targ_mask, out, rows);
}

// round 10
// speedup vs baseline: 1.8599x; 1.8599x over previous
#include <cuda_runtime.h>
#include <math.h>

// SpectralAngleLoss R10: block-per-row smem-atomic scatter (proven 2.61 ns/row),
// gather-form norms, ultra-slim tail: one global atomicAdd per row into a single
// accumulator + tiny finalize kernel (divide, write out, reset). B=8192, N=256.

#define N_PEAKS   256
#define NUM_BINS  2000
#define NB_PAD    2048
#define MAX_ROWS  8192
#define THREADS   256

__device__ float g_accum = 0.0f;   // reset by finalize kernel each replay

__device__ __forceinline__ int mz_bin(float mz) {
    int b = (int)(mz * 2000.0f);           // trunc toward zero == astype(int32)
    return min(max(b, 0), NUM_BINS - 1);
}

__global__ __launch_bounds__(THREADS)
void sal_row(const float* __restrict__ pred_mz,
             const float* __restrict__ pred_int,
             const float* __restrict__ targ_mz,
             const float* __restrict__ targ_int,
             const float* __restrict__ targ_mask)
{
    __shared__ __align__(16) float ph[NB_PAD];
    __shared__ __align__(16) float th[NB_PAD];
    __shared__ float red[3][THREADS / 32];

    const int row = blockIdx.x;
    const int tid = threadIdx.x;

    // ---- zero both histograms (2 STS.128 per thread per array, exact)
    {
        float4 z = make_float4(0.f, 0.f, 0.f, 0.f);
        float4* p4 = (float4*)ph;
        float4* t4 = (float4*)th;
        #pragma unroll
        for (int i = 0; i < NB_PAD / 4 / THREADS; i++) {   // 2 iters
            p4[tid + i * THREADS] = z;
            t4[tid + i * THREADS] = z;
        }
    }

    // ---- coalesced loads, one element per thread
    const int idx = row * N_PEAKS + tid;
    const float ip  = pred_int[idx];
    const float itm = targ_int[idx] * targ_mask[idx];
    const int   bp  = mz_bin(pred_mz[idx]);
    const int   bt  = mz_bin(targ_mz[idx]);
    __syncthreads();

    // ---- scatter: 2 spread smem atomics per thread (the measured floor)
    atomicAdd(&ph[bp], ip);
    atomicAdd(&th[bt], itm);
    __syncthreads();

    // ---- gather-form reductions: 3 LDS per thread, no bin scan
    float dot = ip  * th[bp];
    float pn  = ip  * ph[bp];
    float tn  = itm * th[bt];

    #pragma unroll
    for (int o = 16; o > 0; o >>= 1) {
        dot += __shfl_xor_sync(0xFFFFFFFFu, dot, o);
        pn  += __shfl_xor_sync(0xFFFFFFFFu, pn,  o);
        tn  += __shfl_xor_sync(0xFFFFFFFFu, tn,  o);
    }
    if ((tid & 31) == 0) {
        int w = tid >> 5;
        red[0][w] = dot; red[1][w] = pn; red[2][w] = tn;
    }
    __syncthreads();

    if (tid == 0) {
        float d = 0.f, a = 0.f, b = 0.f;
        #pragma unroll
        for (int w = 0; w < THREADS / 32; w++) {
            d += red[0][w]; a += red[1][w]; b += red[2][w];
        }
        const float eps = 1e-8f;
        float c = d / (fmaxf(sqrtf(a), eps) * fmaxf(sqrtf(b), eps));
        c = fminf(fmaxf(c, -1.0f), 1.0f);
        // fire-and-forget: single global accumulator, no fence/counter/barriers
        atomicAdd(&g_accum, acosf(c));
    }
}

__global__ void sal_finalize(float* __restrict__ out, int rows)
{
    if (threadIdx.x == 0) {
        out[0] = g_accum / ((float)rows * 3.14159265358979323846f);
        g_accum = 0.0f;                    // reset for the next graph replay
    }
}

extern "C" void kernel_launch(void* const* d_in, const int* in_sizes, int n_in,
                              void* d_out, int out_size)
{
    const float* pred_mz   = (const float*)d_in[0];
    const float* pred_int  = (const float*)d_in[1];
    const float* targ_mz   = (const float*)d_in[2];
    const float* targ_int  = (const float*)d_in[3];
    const float* targ_mask = (const float*)d_in[4];
    float* out = (float*)d_out;

    int rows = in_sizes[0] / N_PEAKS;
    if (rows > MAX_ROWS) rows = MAX_ROWS;

    sal_row<<<rows, THREADS>>>(pred_mz, pred_int, targ_mz, targ_int, targ_mask);
    sal_finalize<<<1, 32>>>(out, rows);
}